// round 3
// baseline (speedup 1.0000x reference)
#include <cuda_runtime.h>
#include <math.h>

#define D_MODEL 1024
#define T_FULL 512
#define BATCH 2
#define ROWS (BATCH * T_FULL)   /* 1024 */
#define D_FF 2816
#define IN_FEAT 64
#define NHEAD 16
#define HD 64
#define HD2 32
#define EPS_DEF 1.1920928955078125e-07f
#define EPS_HEAD 1e-05f

// ---------------- scratch (device globals; no allocation allowed) ----------------
__device__ float g_h [ROWS * D_MODEL];
__device__ float g_xn[ROWS * D_MODEL];
__device__ float g_q [ROWS * D_MODEL];
__device__ float g_k [ROWS * D_MODEL];
__device__ float g_v [ROWS * D_MODEL];
__device__ float g_y [ROWS * D_MODEL];
__device__ float g_uv [ROWS * 2 * D_FF];
__device__ float g_act[ROWS * D_FF];

// ---------------- embed: h = concat(sep_emb[sep], x@Wi^T + bi) / sqrt(D) --------
__global__ void embed_kernel(const float* __restrict__ x, const int* __restrict__ sep,
                             const float* __restrict__ sep_emb,
                             const float* __restrict__ Wi, const float* __restrict__ bi) {
    int row = blockIdx.x;
    int b = row >> 9;
    int t = row & 511;
    const float inv = 0.03125f; // 1/sqrt(1024)
    if (t == 0) {
        int idx = sep[b];
        for (int d = threadIdx.x; d < D_MODEL; d += blockDim.x)
            g_h[row * D_MODEL + d] = sep_emb[idx * D_MODEL + d] * inv;
        return;
    }
    __shared__ float xs[IN_FEAT];
    if (threadIdx.x < IN_FEAT)
        xs[threadIdx.x] = x[(b * 511 + (t - 1)) * IN_FEAT + threadIdx.x];
    __syncthreads();
    for (int d = threadIdx.x; d < D_MODEL; d += blockDim.x) {
        float acc = bi[d];
        const float* wr = Wi + d * IN_FEAT;
#pragma unroll
        for (int f = 0; f < IN_FEAT; f++) acc += xs[f] * wr[f];
        g_h[row * D_MODEL + d] = acc * inv;
    }
}

// ---------------- RMSNorm: out = in * rsqrt(mean(in^2)+eps) * w ------------------
__global__ void rms_kernel(const float* __restrict__ in, const float* __restrict__ w,
                           float* __restrict__ out, float eps) {
    int row = blockIdx.x;
    int t = threadIdx.x;
    const float4* inr = (const float4*)(in + row * D_MODEL);
    __shared__ float red[256];
    float ss = 0.f;
    for (int i = t; i < D_MODEL / 4; i += 256) {
        float4 v = inr[i];
        ss += v.x * v.x + v.y * v.y + v.z * v.z + v.w * v.w;
    }
    red[t] = ss;
    __syncthreads();
    for (int s = 128; s > 0; s >>= 1) {
        if (t < s) red[t] += red[t + s];
        __syncthreads();
    }
    float inv = rsqrtf(red[0] / (float)D_MODEL + eps);
    for (int i = t; i < D_MODEL; i += 256)
        out[row * D_MODEL + i] = in[row * D_MODEL + i] * inv * w[i];
}

// ---------------- SGEMM: C[M,N] = A[M,K] @ W[N,K]^T + bias[N] (+C if accum) ------
// 128x128 tile, BK=8, 256 threads, 8x8 micro-tile. All dims divide evenly.
__global__ void sgemm_awt(const float* __restrict__ A, const float* __restrict__ W,
                          const float* __restrict__ bias, float* __restrict__ C,
                          int M, int N, int K, int accum) {
    __shared__ float As[8][128];
    __shared__ float Ws[8][128];
    const int bm = blockIdx.y * 128;
    const int bn = blockIdx.x * 128;
    const int tid = threadIdx.x;
    const int lr = tid >> 1;          // 0..127
    const int lc = (tid & 1) * 4;     // 0 or 4
    const int tm = (tid >> 4) * 8;
    const int tn = (tid & 15) * 8;

    float acc[8][8];
#pragma unroll
    for (int i = 0; i < 8; i++)
#pragma unroll
        for (int j = 0; j < 8; j++) acc[i][j] = 0.f;

    for (int k0 = 0; k0 < K; k0 += 8) {
        float4 a4 = *(const float4*)(A + (size_t)(bm + lr) * K + k0 + lc);
        As[lc + 0][lr] = a4.x; As[lc + 1][lr] = a4.y;
        As[lc + 2][lr] = a4.z; As[lc + 3][lr] = a4.w;
        float4 w4 = *(const float4*)(W + (size_t)(bn + lr) * K + k0 + lc);
        Ws[lc + 0][lr] = w4.x; Ws[lc + 1][lr] = w4.y;
        Ws[lc + 2][lr] = w4.z; Ws[lc + 3][lr] = w4.w;
        __syncthreads();
#pragma unroll
        for (int kk = 0; kk < 8; kk++) {
            float af[8], wf[8];
#pragma unroll
            for (int i = 0; i < 8; i++) af[i] = As[kk][tm + i];
#pragma unroll
            for (int j = 0; j < 8; j++) wf[j] = Ws[kk][tn + j];
#pragma unroll
            for (int i = 0; i < 8; i++)
#pragma unroll
                for (int j = 0; j < 8; j++) acc[i][j] += af[i] * wf[j];
        }
        __syncthreads();
    }

#pragma unroll
    for (int i = 0; i < 8; i++) {
        int m = bm + tm + i;
#pragma unroll
        for (int j = 0; j < 8; j++) {
            int n = bn + tn + j;
            float v = acc[i][j] + bias[n];
            if (accum) v += C[(size_t)m * N + n];
            C[(size_t)m * N + n] = v;
        }
    }
}

// ---------------- RoPE (interleaved pairs), rows t>=1, angle index t-1 -----------
__global__ void rope_kernel(float* __restrict__ q, float* __restrict__ k,
                            const float* __restrict__ cosb, const float* __restrict__ sinb) {
    int idx = blockIdx.x * blockDim.x + threadIdx.x;
    if (idx >= BATCH * 511 * 512) return;
    int within = idx & 511;          // 32 sub-heads * 16 pairs
    int r = idx >> 9;                // 0 .. 2*511-1
    int b = r / 511;
    int t = r % 511 + 1;
    int hh = within >> 4;
    int i = within & 15;
    int row = b * T_FULL + t;
    int col = hh * HD2 + 2 * i;
    float c = cosb[(t - 1) * 16 + i];
    float s = sinb[(t - 1) * 16 + i];
    int o = row * D_MODEL + col;
    float xr = q[o], xi = q[o + 1];
    q[o] = xr * c - xi * s;
    q[o + 1] = xr * s + xi * c;
    xr = k[o]; xi = k[o + 1];
    k[o] = xr * c - xi * s;
    k[o + 1] = xr * s + xi * c;
}

// ---------------- DINT attention: one block per (q, head-pair, batch) ------------
// Output is written in (B, H, T, HD) contiguous order to replicate the
// reference's y.reshape(B, T, D) on a (B, H, T, HD) tensor (a permuting
// reshape that the reference model performs and we must match).
__global__ void attn_kernel(const float* __restrict__ lq1, const float* __restrict__ lq2,
                            const float* __restrict__ lk1, const float* __restrict__ lk2,
                            const float* __restrict__ hw, float lam_init) {
    const int qi = blockIdx.x;
    const int h = blockIdx.y;
    const int b = blockIdx.z;
    const int t = threadIdx.x; // 256 threads
    __shared__ float s0[512], s1[512];
    __shared__ float qv[64];
    __shared__ float red[256];
    __shared__ float ov[64];
    __shared__ float lam_s;

    const int row = b * T_FULL + qi;
    if (t < 64) qv[t] = g_q[row * D_MODEL + h * 64 + t];
    if (t == 0) {
        float a = 0.f, c = 0.f;
        for (int i = 0; i < HD2; i++) { a += lk1[i] * lq1[i]; c += lk2[i] * lq2[i]; }
        lam_s = expf(a) - expf(c) + lam_init;
    }
    __syncthreads();

    const float scale = 0.17677669529663687f; // 1/sqrt(32)
    const int j = t & 3;       // 4 threads cooperate per key
    const int kk0 = t >> 2;    // 0..63
#pragma unroll
    for (int kb = 0; kb < 512; kb += 64) {
        int key = kb + kk0;
        const float* kp = g_k + (size_t)(b * T_FULL + key) * D_MODEL + h * 64;
        int d0 = j * 8;
        float p0 = 0.f, p1 = 0.f;
#pragma unroll
        for (int dd = 0; dd < 8; dd++) {
            p0 += qv[d0 + dd] * kp[d0 + dd];
            p1 += qv[32 + d0 + dd] * kp[32 + d0 + dd];
        }
        p0 += __shfl_xor_sync(0xffffffffu, p0, 1, 4);
        p0 += __shfl_xor_sync(0xffffffffu, p0, 2, 4);
        p1 += __shfl_xor_sync(0xffffffffu, p1, 1, 4);
        p1 += __shfl_xor_sync(0xffffffffu, p1, 2, 4);
        if (j == 0) {
            bool ok = (key <= qi);
            s0[key] = ok ? p0 * scale : -1e9f;
            s1[key] = ok ? p1 * scale : -1e9f;
        }
    }
    __syncthreads();

    // softmax on s0 then s1 (masked entries underflow to exactly 0, matching jnp)
    for (int pass = 0; pass < 2; pass++) {
        float* sp = pass ? s1 : s0;
        float m = fmaxf(sp[t], sp[t + 256]);
        red[t] = m;
        __syncthreads();
        for (int s = 128; s > 0; s >>= 1) {
            if (t < s) red[t] = fmaxf(red[t], red[t + s]);
            __syncthreads();
        }
        m = red[0];
        __syncthreads();
        float e0 = expf(sp[t] - m);
        float e1 = expf(sp[t + 256] - m);
        red[t] = e0 + e1;
        __syncthreads();
        for (int s = 128; s > 0; s >>= 1) {
            if (t < s) red[t] += red[t + s];
            __syncthreads();
        }
        float inv = 1.0f / red[0];
        sp[t] = e0 * inv;
        sp[t + 256] = e1 * inv;
        __syncthreads();
    }

    // differential combine: af = a0 - lam*a1 + (k<=q ? lam/(q+1) : 0)
    const float lam = lam_s;
    const float coef = lam / (float)(qi + 1);
    {
        int k1 = t, k2 = t + 256;
        s0[k1] = s0[k1] - lam * s1[k1] + (k1 <= qi ? coef : 0.f);
        s0[k2] = s0[k2] - lam * s1[k2] + (k2 <= qi ? coef : 0.f);
    }
    __syncthreads();

    // AV: restrict to k<=qi
    const int d = t & 63;
    const int c = t >> 6;
    float acc = 0.f;
    const float* vp = g_v + (size_t)(b * T_FULL) * D_MODEL + h * 64 + d;
    int kbeg = c * 128;
    int kend = min(kbeg + 128, qi + 1);
    for (int key = kbeg; key < kend; key++)
        acc += s0[key] * vp[(size_t)key * D_MODEL];
    red[t] = acc;
    __syncthreads();
    if (t < 64) ov[t] = red[t] + red[t + 64] + red[t + 128] + red[t + 192];
    __syncthreads();

    // per-head RMS with hw, eps 1e-5
    if (t < 64) red[t] = ov[t] * ov[t];
    __syncthreads();
    for (int s = 32; s > 0; s >>= 1) {
        if (t < s) red[t] += red[t + s];
        __syncthreads();
    }
    if (t < 64) {
        float inv = rsqrtf(red[0] / 64.f + EPS_HEAD);
        // (B, H, T, HD) layout — replicates the reference's permuting reshape
        g_y[((size_t)b * NHEAD + h) * (T_FULL * HD) + (size_t)qi * HD + t]
            = ov[t] * inv * hw[t];
    }
}

// ---------------- SiLU gate: act = u * silu(g) ----------------------------------
__global__ void act_kernel() {
    int idx = blockIdx.x * blockDim.x + threadIdx.x;
    if (idx >= ROWS * D_FF) return;
    int m = idx / D_FF;
    int e = idx - m * D_FF;
    float u = g_uv[(size_t)m * 2 * D_FF + e];
    float g = g_uv[(size_t)m * 2 * D_FF + D_FF + e];
    g_act[idx] = u * (g / (1.f + expf(-g)));
}

// ---------------- final: out = rms(h, nfw) @ Wp^T + bp --------------------------
__global__ void final_kernel(const float* __restrict__ nfw, const float* __restrict__ Wp,
                             const float* __restrict__ bp, float* __restrict__ out) {
    int row = blockIdx.x;
    int t = threadIdx.x; // 256
    __shared__ float red[256];
    const float* hr = g_h + (size_t)row * D_MODEL;
    float ss = 0.f;
    for (int dd = t; dd < D_MODEL; dd += 256) { float v = hr[dd]; ss += v * v; }
    red[t] = ss;
    __syncthreads();
    for (int s = 128; s > 0; s >>= 1) {
        if (t < s) red[t] += red[t + s];
        __syncthreads();
    }
    float inv = rsqrtf(red[0] / (float)D_MODEL + EPS_DEF);
    __syncthreads();
    for (int p = 0; p < 4; p++) {
        float acc = 0.f;
        for (int dd = t; dd < D_MODEL; dd += 256)
            acc += hr[dd] * inv * nfw[dd] * Wp[p * D_MODEL + dd];
        red[t] = acc;
        __syncthreads();
        for (int s = 128; s > 0; s >>= 1) {
            if (t < s) red[t] += red[t + s];
            __syncthreads();
        }
        if (t == 0) out[row * 4 + p] = red[0] + bp[p];
        __syncthreads();
    }
}

// ---------------- orchestration --------------------------------------------------
extern "C" void kernel_launch(void* const* d_in, const int* in_sizes, int n_in,
                              void* d_out, int out_size) {
    const float* x       = (const float*)d_in[0];
    const int*   sep     = (const int*)  d_in[1];
    const float* Wq      = (const float*)d_in[2];
    const float* bq      = (const float*)d_in[3];
    const float* Wk      = (const float*)d_in[4];
    const float* bk      = (const float*)d_in[5];
    const float* Wv      = (const float*)d_in[6];
    const float* bv      = (const float*)d_in[7];
    const float* Wo      = (const float*)d_in[8];
    const float* bo      = (const float*)d_in[9];
    const float* lq1     = (const float*)d_in[10];
    const float* lq2     = (const float*)d_in[11];
    const float* lk1     = (const float*)d_in[12];
    const float* lk2     = (const float*)d_in[13];
    const float* hw      = (const float*)d_in[14];
    const float* n1w     = (const float*)d_in[15];
    const float* n2w     = (const float*)d_in[16];
    const float* Wg      = (const float*)d_in[17];
    const float* bg      = (const float*)d_in[18];
    const float* Wf      = (const float*)d_in[19];
    const float* bf      = (const float*)d_in[20];
    const float* Wi      = (const float*)d_in[21];
    const float* bi      = (const float*)d_in[22];
    const float* nfw     = (const float*)d_in[23];
    const float* Wp      = (const float*)d_in[24];
    const float* bp      = (const float*)d_in[25];
    const float* sep_emb = (const float*)d_in[26];
    const float* cosb    = (const float*)d_in[27];
    const float* sinb    = (const float*)d_in[28];

    float *h, *xn, *q, *k, *v, *y, *uv, *act;
    cudaGetSymbolAddress((void**)&h,  g_h);
    cudaGetSymbolAddress((void**)&xn, g_xn);
    cudaGetSymbolAddress((void**)&q,  g_q);
    cudaGetSymbolAddress((void**)&k,  g_k);
    cudaGetSymbolAddress((void**)&v,  g_v);
    cudaGetSymbolAddress((void**)&y,  g_y);
    cudaGetSymbolAddress((void**)&uv, g_uv);
    cudaGetSymbolAddress((void**)&act, g_act);

    embed_kernel<<<ROWS, 256>>>(x, sep, sep_emb, Wi, bi);

    const dim3 gD(D_MODEL / 128, ROWS / 128);       // 8 x 8
    const dim3 gG(2 * D_FF / 128, ROWS / 128);      // 44 x 8

    for (int l = 0; l < 6; l++) {
        float lam_init = (float)(0.8 - 0.6 * exp(-0.3 * (double)l));

        rms_kernel<<<ROWS, 256>>>(h, n1w + l * D_MODEL, xn, EPS_DEF);

        sgemm_awt<<<gD, 256>>>(xn, Wq + (size_t)l * D_MODEL * D_MODEL, bq + l * D_MODEL,
                               q, ROWS, D_MODEL, D_MODEL, 0);
        sgemm_awt<<<gD, 256>>>(xn, Wk + (size_t)l * D_MODEL * D_MODEL, bk + l * D_MODEL,
                               k, ROWS, D_MODEL, D_MODEL, 0);
        sgemm_awt<<<gD, 256>>>(xn, Wv + (size_t)l * D_MODEL * D_MODEL, bv + l * D_MODEL,
                               v, ROWS, D_MODEL, D_MODEL, 0);

        rope_kernel<<<(BATCH * 511 * 512 + 255) / 256, 256>>>(q, k, cosb, sinb);

        attn_kernel<<<dim3(T_FULL, NHEAD, BATCH), 256>>>(
            lq1 + l * HD2, lq2 + l * HD2, lk1 + l * HD2, lk2 + l * HD2,
            hw + l * HD, lam_init);

        sgemm_awt<<<gD, 256>>>(y, Wo + (size_t)l * D_MODEL * D_MODEL, bo + l * D_MODEL,
                               h, ROWS, D_MODEL, D_MODEL, 1);

        rms_kernel<<<ROWS, 256>>>(h, n2w + l * D_MODEL, xn, EPS_DEF);

        sgemm_awt<<<gG, 256>>>(xn, Wg + (size_t)l * 2 * D_FF * D_MODEL, bg + l * 2 * D_FF,
                               uv, ROWS, 2 * D_FF, D_MODEL, 0);

        act_kernel<<<(ROWS * D_FF + 255) / 256, 256>>>();

        sgemm_awt<<<gD, 256>>>(act, Wf + (size_t)l * D_FF * D_MODEL,
                               bf + l * D_MODEL, h, ROWS, D_MODEL, D_FF, 1);
    }

    final_kernel<<<ROWS, 256>>>(nfw, Wp, bp, (float*)d_out);
}

// round 4
// speedup vs baseline: 2.2600x; 2.2600x over previous
#include <cuda_runtime.h>
#include <math.h>

#define D_MODEL 1024
#define T_FULL 512
#define BATCH 2
#define ROWS (BATCH * T_FULL)   /* 1024 */
#define D_FF 2816
#define IN_FEAT 64
#define NHEAD 16
#define HD 64
#define HD2 32
#define EPS_DEF 1.1920928955078125e-07f
#define EPS_HEAD 1e-05f

// ---------------- scratch (device globals; no allocation allowed) ----------------
__device__ float g_h [ROWS * D_MODEL];
__device__ float g_xn[ROWS * D_MODEL];
__device__ float g_q [ROWS * D_MODEL];
__device__ float g_k [ROWS * D_MODEL];
__device__ float g_v [ROWS * D_MODEL];
__device__ float g_y [ROWS * D_MODEL];
__device__ float g_uv [ROWS * 2 * D_FF];
__device__ float g_act[ROWS * D_FF];

// ---------------- embed ----------------------------------------------------------
__global__ void embed_kernel(const float* __restrict__ x, const int* __restrict__ sep,
                             const float* __restrict__ sep_emb,
                             const float* __restrict__ Wi, const float* __restrict__ bi) {
    int row = blockIdx.x;
    int b = row >> 9;
    int t = row & 511;
    const float inv = 0.03125f; // 1/sqrt(1024)
    if (t == 0) {
        int idx = sep[b];
        for (int d = threadIdx.x; d < D_MODEL; d += blockDim.x)
            g_h[row * D_MODEL + d] = sep_emb[idx * D_MODEL + d] * inv;
        return;
    }
    __shared__ float xs[IN_FEAT];
    if (threadIdx.x < IN_FEAT)
        xs[threadIdx.x] = x[(b * 511 + (t - 1)) * IN_FEAT + threadIdx.x];
    __syncthreads();
    for (int d = threadIdx.x; d < D_MODEL; d += blockDim.x) {
        float acc = bi[d];
        const float* wr = Wi + d * IN_FEAT;
#pragma unroll
        for (int f = 0; f < IN_FEAT; f++) acc += xs[f] * wr[f];
        g_h[row * D_MODEL + d] = acc * inv;
    }
}

// ---------------- RMSNorm --------------------------------------------------------
__global__ void rms_kernel(const float* __restrict__ in, const float* __restrict__ w,
                           float* __restrict__ out, float eps) {
    int row = blockIdx.x;
    int t = threadIdx.x;
    const float4* inr = (const float4*)(in + row * D_MODEL);
    __shared__ float red[256];
    float ss = 0.f;
    for (int i = t; i < D_MODEL / 4; i += 256) {
        float4 v = inr[i];
        ss += v.x * v.x + v.y * v.y + v.z * v.z + v.w * v.w;
    }
    red[t] = ss;
    __syncthreads();
    for (int s = 128; s > 0; s >>= 1) {
        if (t < s) red[t] += red[t + s];
        __syncthreads();
    }
    float inv = rsqrtf(red[0] / (float)D_MODEL + eps);
    for (int i = t; i < D_MODEL; i += 256)
        out[row * D_MODEL + i] = in[row * D_MODEL + i] * inv * w[i];
}

// ---------------- TF32 tensor-core GEMM ------------------------------------------
// C[M,N] = A[M,K] @ W[N,K]^T + bias[N] (+C if accum). fp32 in/out, tf32 mma
// with round-to-nearest conversion (cvt.rna) so no truncation bias.
// BM=128, BN=64, BK=32; 8 warps (4 m x 2 n); warp tile 32x32 = 2x4 m16n8k8.
#define BM 128
#define BN 64
#define BK 32
#define BKP 36   /* padded row stride (words): 16B-aligned, conflict-free frags */

__device__ __forceinline__ unsigned f2tf32(float x) {
    unsigned y;
    asm("cvt.rna.tf32.f32 %0, %1;" : "=r"(y) : "f"(x));
    return y;
}

__global__ void __launch_bounds__(256)
gemm_tf32(const float* __restrict__ A, const float* __restrict__ W,
          const float* __restrict__ bias, float* __restrict__ C,
          int M, int N, int K, int accum) {
    __shared__ unsigned As[BM * BKP];
    __shared__ unsigned Ws[BN * BKP];

    const int tid = threadIdx.x;
    const int lane = tid & 31;
    const int wid = tid >> 5;
    const int wm = wid >> 1;       // 0..3
    const int wn = wid & 1;        // 0..1
    const int gid = lane >> 2;     // 0..7
    const int tig = lane & 3;      // 0..3
    const int bm = blockIdx.y * BM;
    const int bn = blockIdx.x * BN;

    float acc[2][4][4];
#pragma unroll
    for (int mt = 0; mt < 2; mt++)
#pragma unroll
        for (int nt = 0; nt < 4; nt++)
#pragma unroll
            for (int r = 0; r < 4; r++) acc[mt][nt][r] = 0.f;

    float4 ra[4], rb[2];
    // load tile at k0 into registers
    const int arow[4] = { (tid + 0) >> 3, (tid + 256) >> 3, (tid + 512) >> 3, (tid + 768) >> 3 };
    const int acol = (tid & 7) * 4;
    const int brow[2] = { (tid + 0) >> 3, (tid + 256) >> 3 };

#define LDG_TILE(k0)                                                              \
    {                                                                             \
        _Pragma("unroll")                                                         \
        for (int i = 0; i < 4; i++)                                               \
            ra[i] = *(const float4*)(A + (size_t)(bm + arow[i]) * K + (k0) + acol); \
        _Pragma("unroll")                                                         \
        for (int i = 0; i < 2; i++)                                               \
            rb[i] = *(const float4*)(W + (size_t)(bn + brow[i]) * K + (k0) + acol); \
    }
#define STS_TILE()                                                                \
    {                                                                             \
        _Pragma("unroll")                                                         \
        for (int i = 0; i < 4; i++) {                                             \
            uint4 u = { f2tf32(ra[i].x), f2tf32(ra[i].y), f2tf32(ra[i].z), f2tf32(ra[i].w) }; \
            *(uint4*)&As[arow[i] * BKP + acol] = u;                               \
        }                                                                         \
        _Pragma("unroll")                                                         \
        for (int i = 0; i < 2; i++) {                                             \
            uint4 u = { f2tf32(rb[i].x), f2tf32(rb[i].y), f2tf32(rb[i].z), f2tf32(rb[i].w) }; \
            *(uint4*)&Ws[brow[i] * BKP + acol] = u;                               \
        }                                                                         \
    }

    LDG_TILE(0);
    STS_TILE();
    __syncthreads();

    const int nit = K / BK;
    for (int it = 0; it < nit; it++) {
        if (it + 1 < nit) LDG_TILE((it + 1) * BK);

#pragma unroll
        for (int ks = 0; ks < 4; ks++) {
            const int k = ks * 8;
            unsigned af[2][4], bf[4][2];
#pragma unroll
            for (int mt = 0; mt < 2; mt++) {
                int r = wm * 32 + mt * 16 + gid;
                af[mt][0] = As[r * BKP + k + tig];
                af[mt][1] = As[(r + 8) * BKP + k + tig];
                af[mt][2] = As[r * BKP + k + tig + 4];
                af[mt][3] = As[(r + 8) * BKP + k + tig + 4];
            }
#pragma unroll
            for (int nt = 0; nt < 4; nt++) {
                int c = wn * 32 + nt * 8 + gid;
                bf[nt][0] = Ws[c * BKP + k + tig];
                bf[nt][1] = Ws[c * BKP + k + tig + 4];
            }
#pragma unroll
            for (int mt = 0; mt < 2; mt++)
#pragma unroll
                for (int nt = 0; nt < 4; nt++) {
                    asm volatile(
                        "mma.sync.aligned.m16n8k8.row.col.f32.tf32.tf32.f32 "
                        "{%0,%1,%2,%3}, {%4,%5,%6,%7}, {%8,%9}, {%0,%1,%2,%3};\n"
                        : "+f"(acc[mt][nt][0]), "+f"(acc[mt][nt][1]),
                          "+f"(acc[mt][nt][2]), "+f"(acc[mt][nt][3])
                        : "r"(af[mt][0]), "r"(af[mt][1]), "r"(af[mt][2]), "r"(af[mt][3]),
                          "r"(bf[nt][0]), "r"(bf[nt][1]));
                }
        }
        __syncthreads();
        if (it + 1 < nit) {
            STS_TILE();
            __syncthreads();
        }
    }

    // epilogue: c0/c1 at (row, 2*tig+{0,1}), c2/c3 at (row+8, ...)
#pragma unroll
    for (int mt = 0; mt < 2; mt++) {
        int r0 = bm + wm * 32 + mt * 16 + gid;
#pragma unroll
        for (int nt = 0; nt < 4; nt++) {
            int c0 = bn + wn * 32 + nt * 8 + 2 * tig;
            float2 b2 = *(const float2*)(bias + c0);
            float* p0 = C + (size_t)r0 * N + c0;
            float* p1 = C + (size_t)(r0 + 8) * N + c0;
            float2 v0 = { acc[mt][nt][0] + b2.x, acc[mt][nt][1] + b2.y };
            float2 v1 = { acc[mt][nt][2] + b2.x, acc[mt][nt][3] + b2.y };
            if (accum) {
                float2 o0 = *(float2*)p0, o1 = *(float2*)p1;
                v0.x += o0.x; v0.y += o0.y;
                v1.x += o1.x; v1.y += o1.y;
            }
            *(float2*)p0 = v0;
            *(float2*)p1 = v1;
        }
    }
}

// ---------------- RoPE ------------------------------------------------------------
__global__ void rope_kernel(float* __restrict__ q, float* __restrict__ k,
                            const float* __restrict__ cosb, const float* __restrict__ sinb) {
    int idx = blockIdx.x * blockDim.x + threadIdx.x;
    if (idx >= BATCH * 511 * 512) return;
    int within = idx & 511;          // 32 sub-heads * 16 pairs
    int r = idx >> 9;
    int b = r / 511;
    int t = r % 511 + 1;
    int hh = within >> 4;
    int i = within & 15;
    int row = b * T_FULL + t;
    int col = hh * HD2 + 2 * i;
    float c = cosb[(t - 1) * 16 + i];
    float s = sinb[(t - 1) * 16 + i];
    int o = row * D_MODEL + col;
    float xr = q[o], xi = q[o + 1];
    q[o] = xr * c - xi * s;
    q[o + 1] = xr * s + xi * c;
    xr = k[o]; xi = k[o + 1];
    k[o] = xr * c - xi * s;
    k[o + 1] = xr * s + xi * c;
}

// ---------------- DINT attention (unchanged, passing version) --------------------
__global__ void attn_kernel(const float* __restrict__ lq1, const float* __restrict__ lq2,
                            const float* __restrict__ lk1, const float* __restrict__ lk2,
                            const float* __restrict__ hw, float lam_init) {
    const int qi = blockIdx.x;
    const int h = blockIdx.y;
    const int b = blockIdx.z;
    const int t = threadIdx.x; // 256 threads
    __shared__ float s0[512], s1[512];
    __shared__ float qv[64];
    __shared__ float red[256];
    __shared__ float ov[64];
    __shared__ float lam_s;

    const int row = b * T_FULL + qi;
    if (t < 64) qv[t] = g_q[row * D_MODEL + h * 64 + t];
    if (t == 0) {
        float a = 0.f, c = 0.f;
        for (int i = 0; i < HD2; i++) { a += lk1[i] * lq1[i]; c += lk2[i] * lq2[i]; }
        lam_s = expf(a) - expf(c) + lam_init;
    }
    __syncthreads();

    const float scale = 0.17677669529663687f; // 1/sqrt(32)
    const int j = t & 3;
    const int kk0 = t >> 2;
#pragma unroll
    for (int kb = 0; kb < 512; kb += 64) {
        int key = kb + kk0;
        const float* kp = g_k + (size_t)(b * T_FULL + key) * D_MODEL + h * 64;
        int d0 = j * 8;
        float p0 = 0.f, p1 = 0.f;
#pragma unroll
        for (int dd = 0; dd < 8; dd++) {
            p0 += qv[d0 + dd] * kp[d0 + dd];
            p1 += qv[32 + d0 + dd] * kp[32 + d0 + dd];
        }
        p0 += __shfl_xor_sync(0xffffffffu, p0, 1, 4);
        p0 += __shfl_xor_sync(0xffffffffu, p0, 2, 4);
        p1 += __shfl_xor_sync(0xffffffffu, p1, 1, 4);
        p1 += __shfl_xor_sync(0xffffffffu, p1, 2, 4);
        if (j == 0) {
            bool ok = (key <= qi);
            s0[key] = ok ? p0 * scale : -1e9f;
            s1[key] = ok ? p1 * scale : -1e9f;
        }
    }
    __syncthreads();

    for (int pass = 0; pass < 2; pass++) {
        float* sp = pass ? s1 : s0;
        float m = fmaxf(sp[t], sp[t + 256]);
        red[t] = m;
        __syncthreads();
        for (int s = 128; s > 0; s >>= 1) {
            if (t < s) red[t] = fmaxf(red[t], red[t + s]);
            __syncthreads();
        }
        m = red[0];
        __syncthreads();
        float e0 = expf(sp[t] - m);
        float e1 = expf(sp[t + 256] - m);
        red[t] = e0 + e1;
        __syncthreads();
        for (int s = 128; s > 0; s >>= 1) {
            if (t < s) red[t] += red[t + s];
            __syncthreads();
        }
        float inv = 1.0f / red[0];
        sp[t] = e0 * inv;
        sp[t + 256] = e1 * inv;
        __syncthreads();
    }

    const float lam = lam_s;
    const float coef = lam / (float)(qi + 1);
    {
        int k1 = t, k2 = t + 256;
        s0[k1] = s0[k1] - lam * s1[k1] + (k1 <= qi ? coef : 0.f);
        s0[k2] = s0[k2] - lam * s1[k2] + (k2 <= qi ? coef : 0.f);
    }
    __syncthreads();

    const int d = t & 63;
    const int c = t >> 6;
    float acc = 0.f;
    const float* vp = g_v + (size_t)(b * T_FULL) * D_MODEL + h * 64 + d;
    int kbeg = c * 128;
    int kend = min(kbeg + 128, qi + 1);
    for (int key = kbeg; key < kend; key++)
        acc += s0[key] * vp[(size_t)key * D_MODEL];
    red[t] = acc;
    __syncthreads();
    if (t < 64) ov[t] = red[t] + red[t + 64] + red[t + 128] + red[t + 192];
    __syncthreads();

    if (t < 64) red[t] = ov[t] * ov[t];
    __syncthreads();
    for (int s = 32; s > 0; s >>= 1) {
        if (t < s) red[t] += red[t + s];
        __syncthreads();
    }
    if (t < 64) {
        float inv = rsqrtf(red[0] / 64.f + EPS_HEAD);
        // (B, H, T, HD) layout — replicates the reference's permuting reshape
        g_y[((size_t)b * NHEAD + h) * (T_FULL * HD) + (size_t)qi * HD + t]
            = ov[t] * inv * hw[t];
    }
}

// ---------------- SiLU gate -------------------------------------------------------
__global__ void act_kernel() {
    int idx = blockIdx.x * blockDim.x + threadIdx.x;
    if (idx >= ROWS * D_FF) return;
    int m = idx / D_FF;
    int e = idx - m * D_FF;
    float u = g_uv[(size_t)m * 2 * D_FF + e];
    float g = g_uv[(size_t)m * 2 * D_FF + D_FF + e];
    g_act[idx] = u * (g / (1.f + expf(-g)));
}

// ---------------- final head ------------------------------------------------------
__global__ void final_kernel(const float* __restrict__ nfw, const float* __restrict__ Wp,
                             const float* __restrict__ bp, float* __restrict__ out) {
    int row = blockIdx.x;
    int t = threadIdx.x; // 256
    __shared__ float red[256];
    const float* hr = g_h + (size_t)row * D_MODEL;
    float ss = 0.f;
    for (int dd = t; dd < D_MODEL; dd += 256) { float v = hr[dd]; ss += v * v; }
    red[t] = ss;
    __syncthreads();
    for (int s = 128; s > 0; s >>= 1) {
        if (t < s) red[t] += red[t + s];
        __syncthreads();
    }
    float inv = rsqrtf(red[0] / (float)D_MODEL + EPS_DEF);
    __syncthreads();
    for (int p = 0; p < 4; p++) {
        float acc = 0.f;
        for (int dd = t; dd < D_MODEL; dd += 256)
            acc += hr[dd] * inv * nfw[dd] * Wp[p * D_MODEL + dd];
        red[t] = acc;
        __syncthreads();
        for (int s = 128; s > 0; s >>= 1) {
            if (t < s) red[t] += red[t + s];
            __syncthreads();
        }
        if (t == 0) out[row * 4 + p] = red[0] + bp[p];
        __syncthreads();
    }
}

// ---------------- orchestration ----------------------------------------------------
extern "C" void kernel_launch(void* const* d_in, const int* in_sizes, int n_in,
                              void* d_out, int out_size) {
    const float* x       = (const float*)d_in[0];
    const int*   sep     = (const int*)  d_in[1];
    const float* Wq      = (const float*)d_in[2];
    const float* bq      = (const float*)d_in[3];
    const float* Wk      = (const float*)d_in[4];
    const float* bk      = (const float*)d_in[5];
    const float* Wv      = (const float*)d_in[6];
    const float* bv      = (const float*)d_in[7];
    const float* Wo      = (const float*)d_in[8];
    const float* bo      = (const float*)d_in[9];
    const float* lq1     = (const float*)d_in[10];
    const float* lq2     = (const float*)d_in[11];
    const float* lk1     = (const float*)d_in[12];
    const float* lk2     = (const float*)d_in[13];
    const float* hw      = (const float*)d_in[14];
    const float* n1w     = (const float*)d_in[15];
    const float* n2w     = (const float*)d_in[16];
    const float* Wg      = (const float*)d_in[17];
    const float* bg      = (const float*)d_in[18];
    const float* Wf      = (const float*)d_in[19];
    const float* bf      = (const float*)d_in[20];
    const float* Wi      = (const float*)d_in[21];
    const float* bi      = (const float*)d_in[22];
    const float* nfw     = (const float*)d_in[23];
    const float* Wp      = (const float*)d_in[24];
    const float* bp      = (const float*)d_in[25];
    const float* sep_emb = (const float*)d_in[26];
    const float* cosb    = (const float*)d_in[27];
    const float* sinb    = (const float*)d_in[28];

    float *h, *xn, *q, *k, *v, *y, *uv, *act;
    cudaGetSymbolAddress((void**)&h,  g_h);
    cudaGetSymbolAddress((void**)&xn, g_xn);
    cudaGetSymbolAddress((void**)&q,  g_q);
    cudaGetSymbolAddress((void**)&k,  g_k);
    cudaGetSymbolAddress((void**)&v,  g_v);
    cudaGetSymbolAddress((void**)&y,  g_y);
    cudaGetSymbolAddress((void**)&uv, g_uv);
    cudaGetSymbolAddress((void**)&act, g_act);

    embed_kernel<<<ROWS, 256>>>(x, sep, sep_emb, Wi, bi);

    const dim3 gD(D_MODEL / BN, ROWS / BM);         // 16 x 8 = 128 blocks
    const dim3 gG(2 * D_FF / BN, ROWS / BM);        // 88 x 8 = 704 blocks

    for (int l = 0; l < 6; l++) {
        float lam_init = (float)(0.8 - 0.6 * exp(-0.3 * (double)l));

        rms_kernel<<<ROWS, 256>>>(h, n1w + l * D_MODEL, xn, EPS_DEF);

        gemm_tf32<<<gD, 256>>>(xn, Wq + (size_t)l * D_MODEL * D_MODEL, bq + l * D_MODEL,
                               q, ROWS, D_MODEL, D_MODEL, 0);
        gemm_tf32<<<gD, 256>>>(xn, Wk + (size_t)l * D_MODEL * D_MODEL, bk + l * D_MODEL,
                               k, ROWS, D_MODEL, D_MODEL, 0);
        gemm_tf32<<<gD, 256>>>(xn, Wv + (size_t)l * D_MODEL * D_MODEL, bv + l * D_MODEL,
                               v, ROWS, D_MODEL, D_MODEL, 0);

        rope_kernel<<<(BATCH * 511 * 512 + 255) / 256, 256>>>(q, k, cosb, sinb);

        attn_kernel<<<dim3(T_FULL, NHEAD, BATCH), 256>>>(
            lq1 + l * HD2, lq2 + l * HD2, lk1 + l * HD2, lk2 + l * HD2,
            hw + l * HD, lam_init);

        gemm_tf32<<<gD, 256>>>(y, Wo + (size_t)l * D_MODEL * D_MODEL, bo + l * D_MODEL,
                               h, ROWS, D_MODEL, D_MODEL, 1);

        rms_kernel<<<ROWS, 256>>>(h, n2w + l * D_MODEL, xn, EPS_DEF);

        gemm_tf32<<<gG, 256>>>(xn, Wg + (size_t)l * 2 * D_FF * D_MODEL, bg + l * 2 * D_FF,
                               uv, ROWS, 2 * D_FF, D_MODEL, 0);

        act_kernel<<<(ROWS * D_FF + 255) / 256, 256>>>();

        gemm_tf32<<<gD, 256>>>(act, Wf + (size_t)l * D_FF * D_MODEL,
                               bf + l * D_MODEL, h, ROWS, D_MODEL, D_FF, 1);
    }

    final_kernel<<<ROWS, 256>>>(nfw, Wp, bp, (float*)d_out);
}

// round 6
// speedup vs baseline: 4.0533x; 1.7935x over previous
#include <cuda_runtime.h>
#include <math.h>

#define D_MODEL 1024
#define T_FULL 512
#define BATCH 2
#define ROWS (BATCH * T_FULL)   /* 1024 */
#define D_FF 2816
#define IN_FEAT 64
#define NHEAD 16
#define HD 64
#define HD2 32
#define EPS_DEF 1.1920928955078125e-07f
#define EPS_HEAD 1e-05f

// ---------------- scratch (device globals; no allocation allowed) ----------------
__device__ float g_h [ROWS * D_MODEL];
__device__ float g_xn[ROWS * D_MODEL];
__device__ float g_q [ROWS * D_MODEL];
__device__ float g_k [ROWS * D_MODEL];
__device__ float g_v [ROWS * D_MODEL];
__device__ float g_y [ROWS * D_MODEL];
__device__ float g_uv [ROWS * 2 * D_FF];
__device__ float g_act[ROWS * D_FF];

// ---------------- embed ----------------------------------------------------------
__global__ void embed_kernel(const float* __restrict__ x, const int* __restrict__ sep,
                             const float* __restrict__ sep_emb,
                             const float* __restrict__ Wi, const float* __restrict__ bi) {
    int row = blockIdx.x;
    int b = row >> 9;
    int t = row & 511;
    const float inv = 0.03125f; // 1/sqrt(1024)
    if (t == 0) {
        int idx = sep[b];
        for (int d = threadIdx.x; d < D_MODEL; d += blockDim.x)
            g_h[row * D_MODEL + d] = sep_emb[idx * D_MODEL + d] * inv;
        return;
    }
    __shared__ float xs[IN_FEAT];
    if (threadIdx.x < IN_FEAT)
        xs[threadIdx.x] = x[(b * 511 + (t - 1)) * IN_FEAT + threadIdx.x];
    __syncthreads();
    for (int d = threadIdx.x; d < D_MODEL; d += blockDim.x) {
        float acc = bi[d];
        const float* wr = Wi + d * IN_FEAT;
#pragma unroll
        for (int f = 0; f < IN_FEAT; f++) acc += xs[f] * wr[f];
        g_h[row * D_MODEL + d] = acc * inv;
    }
}

// ---------------- RMSNorm --------------------------------------------------------
__global__ void rms_kernel(const float* __restrict__ in, const float* __restrict__ w,
                           float* __restrict__ out, float eps) {
    int row = blockIdx.x;
    int t = threadIdx.x;
    const float4* inr = (const float4*)(in + row * D_MODEL);
    __shared__ float red[256];
    float ss = 0.f;
    for (int i = t; i < D_MODEL / 4; i += 256) {
        float4 v = inr[i];
        ss += v.x * v.x + v.y * v.y + v.z * v.z + v.w * v.w;
    }
    red[t] = ss;
    __syncthreads();
    for (int s = 128; s > 0; s >>= 1) {
        if (t < s) red[t] += red[t + s];
        __syncthreads();
    }
    float inv = rsqrtf(red[0] / (float)D_MODEL + eps);
    for (int i = t; i < D_MODEL; i += 256)
        out[row * D_MODEL + i] = in[row * D_MODEL + i] * inv * w[i];
}

// ---------------- TF32 tensor-core GEMM body -------------------------------------
#define BM 128
#define BN 64
#define BK 32
#define BKP 36

__device__ __forceinline__ unsigned f2tf32(float x) {
    unsigned y;
    asm("cvt.rna.tf32.f32 %0, %1;" : "=r"(y) : "f"(x));
    return y;
}

__device__ __forceinline__ void gemm_body(
    const float* __restrict__ A, const float* __restrict__ W,
    const float* __restrict__ bias, float* __restrict__ C,
    int N, int K, int accum, int bm, int bn) {
    __shared__ unsigned As[BM * BKP];
    __shared__ unsigned Ws[BN * BKP];

    const int tid = threadIdx.x;
    const int lane = tid & 31;
    const int wid = tid >> 5;
    const int wm = wid >> 1;
    const int wn = wid & 1;
    const int gid = lane >> 2;
    const int tig = lane & 3;

    float acc[2][4][4];
#pragma unroll
    for (int mt = 0; mt < 2; mt++)
#pragma unroll
        for (int nt = 0; nt < 4; nt++)
#pragma unroll
            for (int r = 0; r < 4; r++) acc[mt][nt][r] = 0.f;

    float4 ra[4], rb[2];
    const int arow[4] = { (tid + 0) >> 3, (tid + 256) >> 3, (tid + 512) >> 3, (tid + 768) >> 3 };
    const int acol = (tid & 7) * 4;
    const int brow[2] = { (tid + 0) >> 3, (tid + 256) >> 3 };

#define LDG_TILE(k0)                                                              \
    {                                                                             \
        _Pragma("unroll")                                                         \
        for (int i = 0; i < 4; i++)                                               \
            ra[i] = *(const float4*)(A + (size_t)(bm + arow[i]) * K + (k0) + acol); \
        _Pragma("unroll")                                                         \
        for (int i = 0; i < 2; i++)                                               \
            rb[i] = *(const float4*)(W + (size_t)(bn + brow[i]) * K + (k0) + acol); \
    }
#define STS_TILE()                                                                \
    {                                                                             \
        _Pragma("unroll")                                                         \
        for (int i = 0; i < 4; i++) {                                             \
            uint4 u = { f2tf32(ra[i].x), f2tf32(ra[i].y), f2tf32(ra[i].z), f2tf32(ra[i].w) }; \
            *(uint4*)&As[arow[i] * BKP + acol] = u;                               \
        }                                                                         \
        _Pragma("unroll")                                                         \
        for (int i = 0; i < 2; i++) {                                             \
            uint4 u = { f2tf32(rb[i].x), f2tf32(rb[i].y), f2tf32(rb[i].z), f2tf32(rb[i].w) }; \
            *(uint4*)&Ws[brow[i] * BKP + acol] = u;                               \
        }                                                                         \
    }

    LDG_TILE(0);
    STS_TILE();
    __syncthreads();

    const int nit = K / BK;
    for (int it = 0; it < nit; it++) {
        if (it + 1 < nit) LDG_TILE((it + 1) * BK);

#pragma unroll
        for (int ks = 0; ks < 4; ks++) {
            const int k = ks * 8;
            unsigned af[2][4], bf[4][2];
#pragma unroll
            for (int mt = 0; mt < 2; mt++) {
                int r = wm * 32 + mt * 16 + gid;
                af[mt][0] = As[r * BKP + k + tig];
                af[mt][1] = As[(r + 8) * BKP + k + tig];
                af[mt][2] = As[r * BKP + k + tig + 4];
                af[mt][3] = As[(r + 8) * BKP + k + tig + 4];
            }
#pragma unroll
            for (int nt = 0; nt < 4; nt++) {
                int c = wn * 32 + nt * 8 + gid;
                bf[nt][0] = Ws[c * BKP + k + tig];
                bf[nt][1] = Ws[c * BKP + k + tig + 4];
            }
#pragma unroll
            for (int mt = 0; mt < 2; mt++)
#pragma unroll
                for (int nt = 0; nt < 4; nt++) {
                    asm volatile(
                        "mma.sync.aligned.m16n8k8.row.col.f32.tf32.tf32.f32 "
                        "{%0,%1,%2,%3}, {%4,%5,%6,%7}, {%8,%9}, {%0,%1,%2,%3};\n"
                        : "+f"(acc[mt][nt][0]), "+f"(acc[mt][nt][1]),
                          "+f"(acc[mt][nt][2]), "+f"(acc[mt][nt][3])
                        : "r"(af[mt][0]), "r"(af[mt][1]), "r"(af[mt][2]), "r"(af[mt][3]),
                          "r"(bf[nt][0]), "r"(bf[nt][1]));
                }
        }
        __syncthreads();
        if (it + 1 < nit) {
            STS_TILE();
            __syncthreads();
        }
    }

#pragma unroll
    for (int mt = 0; mt < 2; mt++) {
        int r0 = bm + wm * 32 + mt * 16 + gid;
#pragma unroll
        for (int nt = 0; nt < 4; nt++) {
            int c0 = bn + wn * 32 + nt * 8 + 2 * tig;
            float2 b2 = *(const float2*)(bias + c0);
            float* p0 = C + (size_t)r0 * N + c0;
            float* p1 = C + (size_t)(r0 + 8) * N + c0;
            float2 v0 = { acc[mt][nt][0] + b2.x, acc[mt][nt][1] + b2.y };
            float2 v1 = { acc[mt][nt][2] + b2.x, acc[mt][nt][3] + b2.y };
            if (accum) {
                float2 o0 = *(float2*)p0, o1 = *(float2*)p1;
                v0.x += o0.x; v0.y += o0.y;
                v1.x += o1.x; v1.y += o1.y;
            }
            *(float2*)p0 = v0;
            *(float2*)p1 = v1;
        }
    }
#undef LDG_TILE
#undef STS_TILE
}

__global__ void __launch_bounds__(256)
gemm_tf32(const float* __restrict__ A, const float* __restrict__ W,
          const float* __restrict__ bias, float* __restrict__ C,
          int N, int K, int accum) {
    gemm_body(A, W, bias, C, N, K, accum, blockIdx.y * BM, blockIdx.x * BN);
}

// fused QKV: grid.x = 48 (3 segments x 16 n-blocks)
__global__ void __launch_bounds__(256)
gemm_qkv(const float* __restrict__ A,
         const float* __restrict__ Wq, const float* __restrict__ Wk, const float* __restrict__ Wv,
         const float* __restrict__ bq, const float* __restrict__ bk, const float* __restrict__ bv) {
    const int seg = blockIdx.x >> 4;
    const int bn = (blockIdx.x & 15) * BN;
    const float* W   = (seg == 0) ? Wq : (seg == 1) ? Wk : Wv;
    const float* bia = (seg == 0) ? bq : (seg == 1) ? bk : bv;
    float* C = (seg == 0) ? g_q : (seg == 1) ? g_k : g_v;
    gemm_body(A, W, bia, C, D_MODEL, D_MODEL, 0, blockIdx.y * BM, bn);
}

// ---------------- RoPE ------------------------------------------------------------
__global__ void rope_kernel(float* __restrict__ q, float* __restrict__ k,
                            const float* __restrict__ cosb, const float* __restrict__ sinb) {
    int idx = blockIdx.x * blockDim.x + threadIdx.x;
    if (idx >= BATCH * 511 * 512) return;
    int within = idx & 511;
    int r = idx >> 9;
    int b = r / 511;
    int t = r % 511 + 1;
    int hh = within >> 4;
    int i = within & 15;
    int row = b * T_FULL + t;
    int col = hh * HD2 + 2 * i;
    float c = cosb[(t - 1) * 16 + i];
    float s = sinb[(t - 1) * 16 + i];
    int o = row * D_MODEL + col;
    float xr = q[o], xi = q[o + 1];
    q[o] = xr * c - xi * s;
    q[o + 1] = xr * s + xi * c;
    xr = k[o]; xi = k[o + 1];
    k[o] = xr * c - xi * s;
    k[o + 1] = xr * s + xi * c;
}

// ---------------- flash DINT attention -------------------------------------------
// Block = (q-tile of 64, head, batch). Two online softmaxes (sub-heads) plus a
// masked V prefix accumulator; per-head RMS fused into epilogue.
// out = o0/l0 - lam*o1/l1 + (lam/(q+1)) * sum_{k<=q} V_k
#define TQ 64
#define SROW 68  /* padded row stride in words */

__global__ void __launch_bounds__(256)
flash_attn(const float* __restrict__ lq1, const float* __restrict__ lq2,
           const float* __restrict__ lk1, const float* __restrict__ lk2,
           const float* __restrict__ hw, float lam_init) {
    extern __shared__ float sm[];
    float* Qs = sm;                 // 64*SROW
    float* Ks = Qs + 64 * SROW;
    float* Vs = Ks + 64 * SROW;
    float* S0 = Vs + 64 * SROW;
    float* S1 = S0 + 64 * SROW;
    __shared__ float lam_sh;

    const int qt = blockIdx.x;      // 0..7
    const int h  = blockIdx.y;
    const int b  = blockIdx.z;
    const int tid = threadIdx.x;
    const int tq0 = qt * TQ;

    if (tid == 0) {
        float a = 0.f, c = 0.f;
#pragma unroll
        for (int i = 0; i < HD2; i++) { a += lk1[i] * lq1[i]; c += lk2[i] * lq2[i]; }
        lam_sh = expf(a) - expf(c) + lam_init;
    }

    // load Q tile (64 x 64)
    {
        const float* qb = g_q + ((size_t)(b * T_FULL + tq0)) * D_MODEL + h * 64;
        for (int i = tid; i < 64 * 16; i += 256) {
            int r = i >> 4, c4 = (i & 15) * 4;
            *(float4*)&Qs[r * SROW + c4] = *(const float4*)(qb + (size_t)r * D_MODEL + c4);
        }
    }
    __syncthreads();

    // AV-partition identities
    const int qq = tid >> 2;             // 0..63 local query
    const int qi = tq0 + qq;             // global query
    const int ds = (tid & 3) * 16;       // 16-dim slice
    // score-partition identities
    const int qg = tid >> 4;             // 0..15
    const int kg = tid & 15;             // 0..15

    float o0[16], o1[16], oS[16];
#pragma unroll
    for (int d = 0; d < 16; d++) { o0[d] = 0.f; o1[d] = 0.f; oS[d] = 0.f; }
    float m0 = -INFINITY, l0 = 0.f, m1 = -INFINITY, l1 = 0.f;
    const float scale = 0.17677669529663687f; // 1/sqrt(32)

    for (int k0 = 0; k0 < tq0 + TQ; k0 += 64) {
        // stage K,V tile
        {
            const float* kb = g_k + ((size_t)(b * T_FULL + k0)) * D_MODEL + h * 64;
            const float* vb = g_v + ((size_t)(b * T_FULL + k0)) * D_MODEL + h * 64;
            for (int i = tid; i < 64 * 16; i += 256) {
                int r = i >> 4, c4 = (i & 15) * 4;
                *(float4*)&Ks[r * SROW + c4] = *(const float4*)(kb + (size_t)r * D_MODEL + c4);
                *(float4*)&Vs[r * SROW + c4] = *(const float4*)(vb + (size_t)r * D_MODEL + c4);
            }
        }
        __syncthreads();

        // scores: 4q x 4k register tile; rows qg+16i / kg+16j
        float s0a[4][4], s1a[4][4];
#pragma unroll
        for (int i = 0; i < 4; i++)
#pragma unroll
            for (int j = 0; j < 4; j++) { s0a[i][j] = 0.f; s1a[i][j] = 0.f; }
#pragma unroll
        for (int d = 0; d < 32; d += 4) {
            float4 qr[4], kr[4];
#pragma unroll
            for (int i = 0; i < 4; i++) qr[i] = *(float4*)&Qs[(qg + 16 * i) * SROW + d];
#pragma unroll
            for (int j = 0; j < 4; j++) kr[j] = *(float4*)&Ks[(kg + 16 * j) * SROW + d];
#pragma unroll
            for (int i = 0; i < 4; i++)
#pragma unroll
                for (int j = 0; j < 4; j++)
                    s0a[i][j] += qr[i].x * kr[j].x + qr[i].y * kr[j].y
                               + qr[i].z * kr[j].z + qr[i].w * kr[j].w;
        }
#pragma unroll
        for (int d = 32; d < 64; d += 4) {
            float4 qr[4], kr[4];
#pragma unroll
            for (int i = 0; i < 4; i++) qr[i] = *(float4*)&Qs[(qg + 16 * i) * SROW + d];
#pragma unroll
            for (int j = 0; j < 4; j++) kr[j] = *(float4*)&Ks[(kg + 16 * j) * SROW + d];
#pragma unroll
            for (int i = 0; i < 4; i++)
#pragma unroll
                for (int j = 0; j < 4; j++)
                    s1a[i][j] += qr[i].x * kr[j].x + qr[i].y * kr[j].y
                               + qr[i].z * kr[j].z + qr[i].w * kr[j].w;
        }
#pragma unroll
        for (int i = 0; i < 4; i++)
#pragma unroll
            for (int j = 0; j < 4; j++) {
                int qrow = qg + 16 * i, krow = kg + 16 * j;
                bool ok = (k0 + krow) <= (tq0 + qrow);
                S0[qrow * SROW + krow] = ok ? s0a[i][j] * scale : -INFINITY;
                S1[qrow * SROW + krow] = ok ? s1a[i][j] * scale : -INFINITY;
            }
        __syncthreads();

        // stats + exp (thread owns 16 keys of its q row; quad covers 64)
        {
            const int kb0 = (tid & 3) * 16;
            float sv0[16], sv1[16];
            float tm0 = -INFINITY, tm1 = -INFINITY;
#pragma unroll
            for (int k = 0; k < 16; k++) {
                sv0[k] = S0[qq * SROW + kb0 + k];
                sv1[k] = S1[qq * SROW + kb0 + k];
                tm0 = fmaxf(tm0, sv0[k]);
                tm1 = fmaxf(tm1, sv1[k]);
            }
            tm0 = fmaxf(tm0, __shfl_xor_sync(0xffffffffu, tm0, 1));
            tm0 = fmaxf(tm0, __shfl_xor_sync(0xffffffffu, tm0, 2));
            tm1 = fmaxf(tm1, __shfl_xor_sync(0xffffffffu, tm1, 1));
            tm1 = fmaxf(tm1, __shfl_xor_sync(0xffffffffu, tm1, 2));
            float nm0 = fmaxf(m0, tm0), nm1 = fmaxf(m1, tm1);
            float ts0 = 0.f, ts1 = 0.f;
#pragma unroll
            for (int k = 0; k < 16; k++) {
                float p0 = __expf(sv0[k] - nm0);
                float p1 = __expf(sv1[k] - nm1);
                ts0 += p0; ts1 += p1;
                S0[qq * SROW + kb0 + k] = p0;
                S1[qq * SROW + kb0 + k] = p1;
            }
            ts0 += __shfl_xor_sync(0xffffffffu, ts0, 1);
            ts0 += __shfl_xor_sync(0xffffffffu, ts0, 2);
            ts1 += __shfl_xor_sync(0xffffffffu, ts1, 1);
            ts1 += __shfl_xor_sync(0xffffffffu, ts1, 2);
            float r0 = __expf(m0 - nm0), r1 = __expf(m1 - nm1);
            l0 = l0 * r0 + ts0; m0 = nm0;
            l1 = l1 * r1 + ts1; m1 = nm1;
#pragma unroll
            for (int d = 0; d < 16; d++) { o0[d] *= r0; o1[d] *= r1; }
        }
        __syncthreads();

        // AV accumulate
        for (int k = 0; k < 64; k++) {
            float p0 = S0[qq * SROW + k];
            float p1 = S1[qq * SROW + k];
            bool ok = (k0 + k) <= qi;
            const float* vp = &Vs[k * SROW + ds];
#pragma unroll
            for (int d4 = 0; d4 < 4; d4++) {
                float4 v = *(float4*)&vp[d4 * 4];
                o0[d4 * 4 + 0] += p0 * v.x; o0[d4 * 4 + 1] += p0 * v.y;
                o0[d4 * 4 + 2] += p0 * v.z; o0[d4 * 4 + 3] += p0 * v.w;
                o1[d4 * 4 + 0] += p1 * v.x; o1[d4 * 4 + 1] += p1 * v.y;
                o1[d4 * 4 + 2] += p1 * v.z; o1[d4 * 4 + 3] += p1 * v.w;
                if (ok) {
                    oS[d4 * 4 + 0] += v.x; oS[d4 * 4 + 1] += v.y;
                    oS[d4 * 4 + 2] += v.z; oS[d4 * 4 + 3] += v.w;
                }
            }
        }
        __syncthreads();
    }

    // epilogue: combine, per-head RMS, write (B,H,T,HD) layout
    {
        float lam = lam_sh;
        float inv0 = 1.f / l0, inv1 = 1.f / l1;
        float coef = lam / (float)(qi + 1);
        float outv[16];
        float ss = 0.f;
#pragma unroll
        for (int d = 0; d < 16; d++) {
            outv[d] = o0[d] * inv0 - lam * (o1[d] * inv1) + coef * oS[d];
            ss += outv[d] * outv[d];
        }
        ss += __shfl_xor_sync(0xffffffffu, ss, 1);
        ss += __shfl_xor_sync(0xffffffffu, ss, 2);
        float rinv = rsqrtf(ss / 64.f + EPS_HEAD);
        float* yb = g_y + (((size_t)(b * NHEAD + h)) * T_FULL + qi) * HD + ds;
#pragma unroll
        for (int d4 = 0; d4 < 4; d4++) {
            float4 w;
            w.x = outv[d4 * 4 + 0] * rinv * hw[ds + d4 * 4 + 0];
            w.y = outv[d4 * 4 + 1] * rinv * hw[ds + d4 * 4 + 1];
            w.z = outv[d4 * 4 + 2] * rinv * hw[ds + d4 * 4 + 2];
            w.w = outv[d4 * 4 + 3] * rinv * hw[ds + d4 * 4 + 3];
            *(float4*)&yb[d4 * 4] = w;
        }
    }
}

// ---------------- SiLU gate -------------------------------------------------------
__global__ void act_kernel() {
    int idx = blockIdx.x * blockDim.x + threadIdx.x;
    if (idx >= ROWS * D_FF) return;
    int m = idx / D_FF;
    int e = idx - m * D_FF;
    float u = g_uv[(size_t)m * 2 * D_FF + e];
    float g = g_uv[(size_t)m * 2 * D_FF + D_FF + e];
    g_act[idx] = u * (g / (1.f + expf(-g)));
}

// ---------------- final head ------------------------------------------------------
__global__ void final_kernel(const float* __restrict__ nfw, const float* __restrict__ Wp,
                             const float* __restrict__ bp, float* __restrict__ out) {
    int row = blockIdx.x;
    int t = threadIdx.x;
    __shared__ float red[256];
    const float* hr = g_h + (size_t)row * D_MODEL;
    float ss = 0.f;
    for (int dd = t; dd < D_MODEL; dd += 256) { float v = hr[dd]; ss += v * v; }
    red[t] = ss;
    __syncthreads();
    for (int s = 128; s > 0; s >>= 1) {
        if (t < s) red[t] += red[t + s];
        __syncthreads();
    }
    float inv = rsqrtf(red[0] / (float)D_MODEL + EPS_DEF);
    __syncthreads();
    for (int p = 0; p < 4; p++) {
        float acc = 0.f;
        for (int dd = t; dd < D_MODEL; dd += 256)
            acc += hr[dd] * inv * nfw[dd] * Wp[p * D_MODEL + dd];
        red[t] = acc;
        __syncthreads();
        for (int s = 128; s > 0; s >>= 1) {
            if (t < s) red[t] += red[t + s];
            __syncthreads();
        }
        if (t == 0) out[row * 4 + p] = red[0] + bp[p];
        __syncthreads();
    }
}

// ---------------- orchestration ----------------------------------------------------
extern "C" void kernel_launch(void* const* d_in, const int* in_sizes, int n_in,
                              void* d_out, int out_size) {
    const float* x       = (const float*)d_in[0];
    const int*   sep     = (const int*)  d_in[1];
    const float* Wq      = (const float*)d_in[2];
    const float* bq      = (const float*)d_in[3];
    const float* Wk      = (const float*)d_in[4];
    const float* bk      = (const float*)d_in[5];
    const float* Wv      = (const float*)d_in[6];
    const float* bv      = (const float*)d_in[7];
    const float* Wo      = (const float*)d_in[8];
    const float* bo      = (const float*)d_in[9];
    const float* lq1     = (const float*)d_in[10];
    const float* lq2     = (const float*)d_in[11];
    const float* lk1     = (const float*)d_in[12];
    const float* lk2     = (const float*)d_in[13];
    const float* hw      = (const float*)d_in[14];
    const float* n1w     = (const float*)d_in[15];
    const float* n2w     = (const float*)d_in[16];
    const float* Wg      = (const float*)d_in[17];
    const float* bg      = (const float*)d_in[18];
    const float* Wf      = (const float*)d_in[19];
    const float* bf      = (const float*)d_in[20];
    const float* Wi      = (const float*)d_in[21];
    const float* bi      = (const float*)d_in[22];
    const float* nfw     = (const float*)d_in[23];
    const float* Wp      = (const float*)d_in[24];
    const float* bp      = (const float*)d_in[25];
    const float* sep_emb = (const float*)d_in[26];
    const float* cosb    = (const float*)d_in[27];
    const float* sinb    = (const float*)d_in[28];

    float *h, *xn, *q, *k, *v, *y, *uv, *act;
    cudaGetSymbolAddress((void**)&h,  g_h);
    cudaGetSymbolAddress((void**)&xn, g_xn);
    cudaGetSymbolAddress((void**)&q,  g_q);
    cudaGetSymbolAddress((void**)&k,  g_k);
    cudaGetSymbolAddress((void**)&v,  g_v);
    cudaGetSymbolAddress((void**)&y,  g_y);
    cudaGetSymbolAddress((void**)&uv, g_uv);
    cudaGetSymbolAddress((void**)&act, g_act);

    const int flash_smem = 5 * 64 * SROW * 4;   // 87040 bytes
    cudaFuncSetAttribute(flash_attn, cudaFuncAttributeMaxDynamicSharedMemorySize, flash_smem);

    embed_kernel<<<ROWS, 256>>>(x, sep, sep_emb, Wi, bi);

    const dim3 gQKV(48, ROWS / BM);                 // 3*16 x 8 = 384 blocks
    const dim3 gD(D_MODEL / BN, ROWS / BM);         // 16 x 8
    const dim3 gG(2 * D_FF / BN, ROWS / BM);        // 88 x 8
    const dim3 gA(T_FULL / TQ, NHEAD, BATCH);       // 8 x 16 x 2

    for (int l = 0; l < 6; l++) {
        float lam_init = (float)(0.8 - 0.6 * exp(-0.3 * (double)l));

        rms_kernel<<<ROWS, 256>>>(h, n1w + l * D_MODEL, xn, EPS_DEF);

        gemm_qkv<<<gQKV, 256>>>(xn,
                                Wq + (size_t)l * D_MODEL * D_MODEL,
                                Wk + (size_t)l * D_MODEL * D_MODEL,
                                Wv + (size_t)l * D_MODEL * D_MODEL,
                                bq + l * D_MODEL, bk + l * D_MODEL, bv + l * D_MODEL);

        rope_kernel<<<(BATCH * 511 * 512 + 255) / 256, 256>>>(q, k, cosb, sinb);

        flash_attn<<<gA, 256, flash_smem>>>(
            lq1 + l * HD2, lq2 + l * HD2, lk1 + l * HD2, lk2 + l * HD2,
            hw + l * HD, lam_init);

        gemm_tf32<<<gD, 256>>>(y, Wo + (size_t)l * D_MODEL * D_MODEL, bo + l * D_MODEL,
                               h, D_MODEL, D_MODEL, 1);

        rms_kernel<<<ROWS, 256>>>(h, n2w + l * D_MODEL, xn, EPS_DEF);

        gemm_tf32<<<gG, 256>>>(xn, Wg + (size_t)l * 2 * D_FF * D_MODEL, bg + l * 2 * D_FF,
                               uv, 2 * D_FF, D_MODEL, 0);

        act_kernel<<<(ROWS * D_FF + 255) / 256, 256>>>();

        gemm_tf32<<<gD, 256>>>(act, Wf + (size_t)l * D_FF * D_MODEL,
                               bf + l * D_MODEL, h, D_MODEL, D_FF, 1);
    }

    final_kernel<<<ROWS, 256>>>(nfw, Wp, bp, (float*)d_out);
}